// round 3
// baseline (speedup 1.0000x reference)
#include <cuda_runtime.h>
#include <math.h>

#define BB 2
#define SS 2048
#define DD 1024
#define HH 16
#define HD 64

// Scratch: projected Q,K,V in [B,H,S,HD] layout (16 MB each, static device arrays)
__device__ float g_Q[BB * HH * SS * HD];
__device__ float g_K[BB * HH * SS * HD];
__device__ float g_V[BB * HH * SS * HD];
__device__ int g_klen[BB];
__device__ int g_qlen[BB];

// ---------------------------------------------------------------------------
// Mask lengths. Masks are valid-prefix (pos < len) so the count of true
// elements equals the length. Dtype-robust: harness may store bool as 1 byte
// or as int32 (4 bytes, little-endian). Since key/query 0 is always valid,
// byte[1] of the buffer is 1 for the 1-byte layout and 0 for the 4-byte
// layout. In BOTH layouts each true element contributes exactly one nonzero
// byte, so counting nonzero bytes over SS*width bytes yields the length.
// ---------------------------------------------------------------------------
__global__ void len_kernel(const unsigned char* __restrict__ km,
                           const unsigned char* __restrict__ qm) {
    int b = blockIdx.x;
    __shared__ int sk[256];
    __shared__ int sq[256];
    int tid = threadIdx.x;

    // Detect element width from buffer head (same for both masks).
    int wk = (km[1] | km[2] | km[3]) ? 1 : 4;
    int wq = (qm[1] | qm[2] | qm[3]) ? 1 : 4;

    int ck = 0, cq = 0;
    for (int i = tid; i < SS * wk; i += 256) ck += (km[(size_t)b * SS * wk + i] != 0);
    for (int i = tid; i < SS * wq; i += 256) cq += (qm[(size_t)b * SS * wq + i] != 0);
    sk[tid] = ck; sq[tid] = cq;
    __syncthreads();
    for (int s = 128; s > 0; s >>= 1) {
        if (tid < s) { sk[tid] += sk[tid + s]; sq[tid] += sq[tid + s]; }
        __syncthreads();
    }
    if (tid == 0) { g_klen[b] = sk[0]; g_qlen[b] = sq[0]; }
}

// ---------------------------------------------------------------------------
// Projection GEMM: C[row, col] = sum_k X[row,k] * W[col,k] + bias[col]
// Output written in head-split layout [B,H,S,HD].
// Tile: BM=64, BN=64, BK=16; 256 threads, 4x4 microtile each.
// which: 0 -> g_Q, 1 -> g_K, 2 -> g_V
// ---------------------------------------------------------------------------
__global__ __launch_bounds__(256) void proj_kernel(
    const float* __restrict__ X, const float* __restrict__ W,
    const float* __restrict__ bias, int which) {
    __shared__ float As[16][68];  // [k][m], padded
    __shared__ float Ws[16][68];  // [k][n], padded

    const int n0 = blockIdx.x * 64;
    const int m0 = blockIdx.y * 64;
    const int tid = threadIdx.x;
    const int tx = tid & 15;
    const int ty = tid >> 4;
    const int lr = tid >> 2;        // 0..63 row within tile for loads
    const int lk = (tid & 3) * 4;   // k offset within 16-wide k-tile

    float acc[4][4] = {};

    for (int k0 = 0; k0 < DD; k0 += 16) {
        float4 a = *(const float4*)&X[(size_t)(m0 + lr) * DD + k0 + lk];
        float4 w = *(const float4*)&W[(size_t)(n0 + lr) * DD + k0 + lk];
        As[lk + 0][lr] = a.x; As[lk + 1][lr] = a.y;
        As[lk + 2][lr] = a.z; As[lk + 3][lr] = a.w;
        Ws[lk + 0][lr] = w.x; Ws[lk + 1][lr] = w.y;
        Ws[lk + 2][lr] = w.z; Ws[lk + 3][lr] = w.w;
        __syncthreads();
#pragma unroll
        for (int kk = 0; kk < 16; kk++) {
            float4 a4 = *(float4*)&As[kk][ty * 4];
            float4 b4 = *(float4*)&Ws[kk][tx * 4];
            float av[4] = {a4.x, a4.y, a4.z, a4.w};
            float bv[4] = {b4.x, b4.y, b4.z, b4.w};
#pragma unroll
            for (int i = 0; i < 4; i++)
#pragma unroll
                for (int j = 0; j < 4; j++)
                    acc[i][j] = fmaf(av[i], bv[j], acc[i][j]);
        }
        __syncthreads();
    }

    // Epilogue: bias + store in [B,H,S,HD] layout. n-tile == head (BN == HD).
    const int h = blockIdx.x;
    float4 bvec = *(const float4*)&bias[n0 + tx * 4];
    float* dst = (which == 0) ? g_Q : (which == 1) ? g_K : g_V;
#pragma unroll
    for (int i = 0; i < 4; i++) {
        int row_g = m0 + ty * 4 + i;
        int b = row_g >> 11;        // / SS
        int s = row_g & (SS - 1);
        float4 o;
        o.x = acc[i][0] + bvec.x;
        o.y = acc[i][1] + bvec.y;
        o.z = acc[i][2] + bvec.z;
        o.w = acc[i][3] + bvec.w;
        *(float4*)&dst[(size_t)((b * HH + h) * SS + s) * HD + tx * 4] = o;
    }
}

// ---------------------------------------------------------------------------
// Flash attention: per (q-tile 64, head, batch). Online softmax, causal +
// key-padding mask, query-padding rows -> pure residual, fused +q epilogue.
// ---------------------------------------------------------------------------
#define ATTN_SMEM_FLOATS (4 * 64 * 68 + 3 * 64)

__global__ __launch_bounds__(256) void attn_kernel(
    const float* __restrict__ qin, float* __restrict__ out) {
    extern __shared__ float smem[];
    float (*Qs)[68]  = (float(*)[68])(smem);                // [q][d]
    float (*Kst)[68] = (float(*)[68])(smem + 64 * 68);      // [d][k] (transposed)
    float (*Vs)[68]  = (float(*)[68])(smem + 2 * 64 * 68);  // [k][d]
    float (*Ps)[68]  = (float(*)[68])(smem + 3 * 64 * 68);  // [q][k]
    float* m_sh = smem + 4 * 64 * 68;
    float* l_sh = m_sh + 64;
    float* alpha_sh = l_sh + 64;

    const int qt = blockIdx.x;
    const int h  = blockIdx.y;
    const int b  = blockIdx.z;
    const int q0 = qt * 64;
    const int klen = g_klen[b];
    const int qlen = g_qlen[b];

    const int tid = threadIdx.x;
    const int tx = tid & 15;
    const int ty = tid >> 4;

    // Fully padded q-tile: out = residual only.
    if (q0 >= qlen) {
#pragma unroll
        for (int i = 0; i < 4; i++) {
            int qq = q0 + ty * 4 + i;
            size_t oidx = (size_t)(b * SS + qq) * DD + h * HD + tx * 4;
            *(float4*)&out[oidx] = *(const float4*)&qin[oidx];
        }
        return;
    }

    const float* Qb = g_Q + (size_t)((b * HH + h) * SS) * HD;
    const float* Kb = g_K + (size_t)((b * HH + h) * SS) * HD;
    const float* Vb = g_V + (size_t)((b * HH + h) * SS) * HD;

    const int lrow = tid >> 2;          // 0..63
    const int dseg = (tid & 3) * 16;    // 0,16,32,48

    // Load Q tile
#pragma unroll
    for (int c = 0; c < 4; c++) {
        *(float4*)&Qs[lrow][dseg + 4 * c] =
            *(const float4*)&Qb[(size_t)(q0 + lrow) * HD + dseg + 4 * c];
    }
    if (tid < 64) { m_sh[tid] = -INFINITY; l_sh[tid] = 0.0f; }

    float acc[4][4] = {};
    const int kend = min(klen, q0 + 64);

    for (int k0 = 0; k0 < kend; k0 += 64) {
        __syncthreads();
        // Load K (transposed) and V tiles
#pragma unroll
        for (int c = 0; c < 4; c++) {
            float4 kv = *(const float4*)&Kb[(size_t)(k0 + lrow) * HD + dseg + 4 * c];
            Kst[dseg + 4 * c + 0][lrow] = kv.x;
            Kst[dseg + 4 * c + 1][lrow] = kv.y;
            Kst[dseg + 4 * c + 2][lrow] = kv.z;
            Kst[dseg + 4 * c + 3][lrow] = kv.w;
            *(float4*)&Vs[lrow][dseg + 4 * c] =
                *(const float4*)&Vb[(size_t)(k0 + lrow) * HD + dseg + 4 * c];
        }
        __syncthreads();

        // S = Q K^T (4x4 per thread)
        float s[4][4] = {};
#pragma unroll 8
        for (int d = 0; d < 64; d++) {
            float qv[4];
#pragma unroll
            for (int i = 0; i < 4; i++) qv[i] = Qs[ty * 4 + i][d];
            float4 k4 = *(float4*)&Kst[d][tx * 4];
            float kv[4] = {k4.x, k4.y, k4.z, k4.w};
#pragma unroll
            for (int i = 0; i < 4; i++)
#pragma unroll
                for (int j = 0; j < 4; j++)
                    s[i][j] = fmaf(qv[i], kv[j], s[i][j]);
        }
        // scale + mask -> Ps
#pragma unroll
        for (int i = 0; i < 4; i++) {
            int qq = q0 + ty * 4 + i;
#pragma unroll
            for (int j = 0; j < 4; j++) {
                int kk = k0 + tx * 4 + j;
                float val = s[i][j] * 0.125f;
                if (kk > qq || kk >= klen) val = -INFINITY;
                Ps[ty * 4 + i][tx * 4 + j] = val;
            }
        }
        __syncthreads();

        // Online softmax: 4 lanes per row (row = tid>>2, seg = tid&3)
        {
            int row = tid >> 2;
            int seg = tid & 3;
            float mloc = -INFINITY;
#pragma unroll
            for (int t = 0; t < 16; t++)
                mloc = fmaxf(mloc, Ps[row][seg * 16 + t]);
            mloc = fmaxf(mloc, __shfl_xor_sync(0xffffffffu, mloc, 1));
            mloc = fmaxf(mloc, __shfl_xor_sync(0xffffffffu, mloc, 2));
            float mold = m_sh[row];
            float mnew = fmaxf(mold, mloc);
            if (mnew == -INFINITY) {
                // entire row masked so far (q above causal band for this tile)
#pragma unroll
                for (int t = 0; t < 16; t++) Ps[row][seg * 16 + t] = 0.0f;
                if (seg == 0) alpha_sh[row] = 1.0f;
            } else {
                float sum = 0.0f;
#pragma unroll
                for (int t = 0; t < 16; t++) {
                    float p = __expf(Ps[row][seg * 16 + t] - mnew);
                    Ps[row][seg * 16 + t] = p;
                    sum += p;
                }
                sum += __shfl_xor_sync(0xffffffffu, sum, 1);
                sum += __shfl_xor_sync(0xffffffffu, sum, 2);
                float alpha = (mold == -INFINITY) ? 0.0f : __expf(mold - mnew);
                if (seg == 0) {
                    m_sh[row] = mnew;
                    l_sh[row] = l_sh[row] * alpha + sum;
                    alpha_sh[row] = alpha;
                }
            }
        }
        __syncthreads();

        // O = O*alpha + P V
        float al[4];
#pragma unroll
        for (int i = 0; i < 4; i++) al[i] = alpha_sh[ty * 4 + i];
#pragma unroll
        for (int i = 0; i < 4; i++)
#pragma unroll
            for (int j = 0; j < 4; j++) acc[i][j] *= al[i];
#pragma unroll 8
        for (int kk = 0; kk < 64; kk++) {
            float pv[4];
#pragma unroll
            for (int i = 0; i < 4; i++) pv[i] = Ps[ty * 4 + i][kk];
            float4 v4 = *(float4*)&Vs[kk][tx * 4];
            float vv[4] = {v4.x, v4.y, v4.z, v4.w};
#pragma unroll
            for (int i = 0; i < 4; i++)
#pragma unroll
                for (int j = 0; j < 4; j++)
                    acc[i][j] = fmaf(pv[i], vv[j], acc[i][j]);
        }
    }

    // Epilogue: normalize, residual, query-padding override.
#pragma unroll
    for (int i = 0; i < 4; i++) {
        int qq = q0 + ty * 4 + i;
        float l = l_sh[ty * 4 + i];
        float inv = (l > 0.0f) ? (1.0f / l) : 0.0f;
        size_t oidx = (size_t)(b * SS + qq) * DD + h * HD + tx * 4;
        float4 r = *(const float4*)&qin[oidx];
        float4 o;
        if (qq >= qlen) {
            o = r;
        } else {
            o.x = acc[i][0] * inv + r.x;
            o.y = acc[i][1] * inv + r.y;
            o.z = acc[i][2] * inv + r.z;
            o.w = acc[i][3] * inv + r.w;
        }
        *(float4*)&out[oidx] = o;
    }
}

// ---------------------------------------------------------------------------
extern "C" void kernel_launch(void* const* d_in, const int* in_sizes, int n_in,
                              void* d_out, int out_size) {
    const float* q  = (const float*)d_in[0];
    const float* k  = (const float*)d_in[1];
    const float* v  = (const float*)d_in[2];
    const float* Wq = (const float*)d_in[3];
    const float* bq = (const float*)d_in[4];
    const float* Wk = (const float*)d_in[5];
    const float* bk = (const float*)d_in[6];
    const float* Wv = (const float*)d_in[7];
    const float* bv = (const float*)d_in[8];
    const unsigned char* km = (const unsigned char*)d_in[9];
    const unsigned char* qm = (const unsigned char*)d_in[10];
    float* out = (float*)d_out;

    static bool attr_set = false;
    if (!attr_set) {
        cudaFuncSetAttribute(attn_kernel,
                             cudaFuncAttributeMaxDynamicSharedMemorySize,
                             ATTN_SMEM_FLOATS * (int)sizeof(float));
        attr_set = true;
    }

    len_kernel<<<BB, 256>>>(km, qm);

    dim3 pg(DD / 64, (BB * SS) / 64);
    proj_kernel<<<pg, 256>>>(q, Wq, bq, 0);
    proj_kernel<<<pg, 256>>>(k, Wk, bk, 1);
    proj_kernel<<<pg, 256>>>(v, Wv, bv, 2);

    dim3 ag(SS / 64, HH, BB);
    attn_kernel<<<ag, 256, ATTN_SMEM_FLOATS * (int)sizeof(float)>>>(q, out);
}

// round 5
// speedup vs baseline: 2.4300x; 2.4300x over previous
#include <cuda_runtime.h>
#include <math.h>

#define BB 2
#define SS 2048
#define DD 1024
#define HH 16
#define HD 64

// Scratch: projected Q,K in [B,H,S,HD]; V transposed in [B,H,HD,S]
__device__ float g_Q[BB * HH * SS * HD];
__device__ float g_K[BB * HH * SS * HD];
__device__ float g_V[BB * HH * SS * HD];   // [B,H,HD,S] layout!
__device__ int g_klen[BB];
__device__ int g_qlen[BB];

// ---------------------------------------------------------------------------
__device__ __forceinline__ unsigned tf32u(float x) {
    unsigned u; asm("cvt.rna.tf32.f32 %0, %1;" : "=r"(u) : "f"(x)); return u;
}
__device__ __forceinline__ float tf32f(float x) {
    return __uint_as_float(tf32u(x));
}
__device__ __forceinline__ void mma8(float& c0, float& c1, float& c2, float& c3,
                                     unsigned a0, unsigned a1, unsigned a2, unsigned a3,
                                     unsigned b0, unsigned b1) {
    asm volatile(
        "mma.sync.aligned.m16n8k8.row.col.f32.tf32.tf32.f32 "
        "{%0,%1,%2,%3},{%4,%5,%6,%7},{%8,%9},{%0,%1,%2,%3};"
        : "+f"(c0), "+f"(c1), "+f"(c2), "+f"(c3)
        : "r"(a0), "r"(a1), "r"(a2), "r"(a3), "r"(b0), "r"(b1));
}

// ---------------------------------------------------------------------------
// Mask lengths (dtype-robust: bool-1B or int32-4B; counts nonzero bytes).
// ---------------------------------------------------------------------------
__global__ void len_kernel(const unsigned char* __restrict__ km,
                           const unsigned char* __restrict__ qm) {
    int b = blockIdx.x;
    __shared__ int sk[256];
    __shared__ int sq[256];
    int tid = threadIdx.x;
    int wk = (km[1] | km[2] | km[3]) ? 1 : 4;
    int wq = (qm[1] | qm[2] | qm[3]) ? 1 : 4;
    int ck = 0, cq = 0;
    for (int i = tid; i < SS * wk; i += 256) ck += (km[(size_t)b * SS * wk + i] != 0);
    for (int i = tid; i < SS * wq; i += 256) cq += (qm[(size_t)b * SS * wq + i] != 0);
    sk[tid] = ck; sq[tid] = cq;
    __syncthreads();
    for (int s = 128; s > 0; s >>= 1) {
        if (tid < s) { sk[tid] += sk[tid + s]; sq[tid] += sq[tid + s]; }
        __syncthreads();
    }
    if (tid == 0) { g_klen[b] = sk[0]; g_qlen[b] = sq[0]; }
}

// ---------------------------------------------------------------------------
// Projection GEMM (tf32 tensor cores): C[m,n] = sum_k X[m,k]*W[n,k] + bias[n]
// BM=128, BN=64(=1 head), BK=32. 8 warps in 4(m)x2(n); warp tile 32x32.
// which: 0 -> g_Q [B,H,S,HD], 1 -> g_K [B,H,S,HD], 2 -> g_V [B,H,HD,S] (transposed)
// ---------------------------------------------------------------------------
#define PLD 36
__global__ __launch_bounds__(256) void proj_kernel(
    const float* __restrict__ X, const float* __restrict__ W,
    const float* __restrict__ bias, int which) {
    __shared__ float As[128][PLD];
    __shared__ float Bs[64][PLD];

    const int tid = threadIdx.x;
    const int lane = tid & 31;
    const int wid = tid >> 5;
    const int g = lane >> 2;   // 0..7
    const int t = lane & 3;    // 0..3
    const int wy = wid & 3;    // m quadrant (32 rows)
    const int wx = wid >> 2;   // n half (32 cols)
    const int n0 = blockIdx.x * 64;
    const int m0 = blockIdx.y * 128;

    float acc[2][4][4];
#pragma unroll
    for (int mi = 0; mi < 2; mi++)
#pragma unroll
        for (int j = 0; j < 4; j++)
#pragma unroll
            for (int c = 0; c < 4; c++) acc[mi][j][c] = 0.0f;

    for (int k0 = 0; k0 < DD; k0 += 32) {
        // Load A: 128x32 floats, cvt to tf32
#pragma unroll
        for (int i = 0; i < 4; i++) {
            int cidx = tid + 256 * i;
            int row = cidx >> 3;
            int ch = (cidx & 7) * 4;
            float4 a = *(const float4*)&X[(size_t)(m0 + row) * DD + k0 + ch];
            As[row][ch + 0] = tf32f(a.x);
            As[row][ch + 1] = tf32f(a.y);
            As[row][ch + 2] = tf32f(a.z);
            As[row][ch + 3] = tf32f(a.w);
        }
        // Load B: 64x32 floats
#pragma unroll
        for (int i = 0; i < 2; i++) {
            int cidx = tid + 256 * i;
            int row = cidx >> 3;
            int ch = (cidx & 7) * 4;
            float4 w = *(const float4*)&W[(size_t)(n0 + row) * DD + k0 + ch];
            Bs[row][ch + 0] = tf32f(w.x);
            Bs[row][ch + 1] = tf32f(w.y);
            Bs[row][ch + 2] = tf32f(w.z);
            Bs[row][ch + 3] = tf32f(w.w);
        }
        __syncthreads();

#pragma unroll
        for (int ks = 0; ks < 4; ks++) {
            unsigned a[2][4];
#pragma unroll
            for (int mi = 0; mi < 2; mi++) {
                int r = wy * 32 + mi * 16;
                int kc = ks * 8;
                a[mi][0] = __float_as_uint(As[r + g][kc + t]);
                a[mi][1] = __float_as_uint(As[r + 8 + g][kc + t]);
                a[mi][2] = __float_as_uint(As[r + g][kc + t + 4]);
                a[mi][3] = __float_as_uint(As[r + 8 + g][kc + t + 4]);
            }
#pragma unroll
            for (int j = 0; j < 4; j++) {
                int nr = wx * 32 + j * 8 + g;
                int kc = ks * 8;
                unsigned b0 = __float_as_uint(Bs[nr][kc + t]);
                unsigned b1 = __float_as_uint(Bs[nr][kc + t + 4]);
#pragma unroll
                for (int mi = 0; mi < 2; mi++)
                    mma8(acc[mi][j][0], acc[mi][j][1], acc[mi][j][2], acc[mi][j][3],
                         a[mi][0], a[mi][1], a[mi][2], a[mi][3], b0, b1);
            }
        }
        __syncthreads();
    }

    // Epilogue. n-tile == head h.
    const int h = blockIdx.x;
    float* dst = (which == 0) ? g_Q : (which == 1) ? g_K : g_V;
#pragma unroll
    for (int mi = 0; mi < 2; mi++) {
#pragma unroll
        for (int j = 0; j < 4; j++) {
            int c = wx * 32 + j * 8 + 2 * t;         // col within head
            float b0v = bias[n0 + c];
            float b1v = bias[n0 + c + 1];
#pragma unroll
            for (int half = 0; half < 2; half++) {
                int r = m0 + wy * 32 + mi * 16 + g + half * 8;
                int b = r >> 11;
                int s = r & (SS - 1);
                float v0 = acc[mi][j][half * 2 + 0] + b0v;
                float v1 = acc[mi][j][half * 2 + 1] + b1v;
                if (which == 2) {
                    // transposed: [B,H,HD,S]
                    dst[((size_t)((b * HH + h) * HD) + c) * SS + s] = v0;
                    dst[((size_t)((b * HH + h) * HD) + c + 1) * SS + s] = v1;
                } else {
                    float2 o = make_float2(v0, v1);
                    *(float2*)&dst[((size_t)((b * HH + h) * SS) + s) * HD + c] = o;
                }
            }
        }
    }
}

// ---------------------------------------------------------------------------
// Flash attention with tf32 tensor-core MMAs.
// 64x64 tiles. 8 warps: wy=wid&3 -> 16 q-rows, wx=wid>>2 -> 32 cols.
// ---------------------------------------------------------------------------
#define ALD 68
#define ATTN_SMEM_FLOATS (4 * 64 * ALD + 3 * 64)

__global__ __launch_bounds__(256) void attn_kernel(
    const float* __restrict__ qin, float* __restrict__ out) {
    extern __shared__ float smem[];
    float (*Qs)[ALD] = (float(*)[ALD])(smem);                 // [q][d]  tf32
    float (*Ks)[ALD] = (float(*)[ALD])(smem + 64 * ALD);      // [kpos][d] tf32
    float (*Vt)[ALD] = (float(*)[ALD])(smem + 2 * 64 * ALD);  // [d][kpos] tf32
    float (*Ps)[ALD] = (float(*)[ALD])(smem + 3 * 64 * ALD);  // [q][kpos] fp32
    float* m_sh = smem + 4 * 64 * ALD;
    float* l_sh = m_sh + 64;
    float* alpha_sh = l_sh + 64;

    const int qt = blockIdx.x;
    const int h  = blockIdx.y;
    const int b  = blockIdx.z;
    const int q0 = qt * 64;
    const int klen = g_klen[b];
    const int qlen = g_qlen[b];

    const int tid = threadIdx.x;
    const int lane = tid & 31;
    const int wid = tid >> 5;
    const int g = lane >> 2;
    const int t = lane & 3;
    const int wy = wid & 3;   // q band: 16 rows
    const int wx = wid >> 2;  // col half: 32

    // Fully padded q-tile: residual only.
    if (q0 >= qlen) {
        int lrow = tid >> 2;
        int dseg = (tid & 3) * 16;
#pragma unroll
        for (int c = 0; c < 4; c++) {
            size_t oidx = (size_t)(b * SS + q0 + lrow) * DD + h * HD + dseg + 4 * c;
            *(float4*)&out[oidx] = *(const float4*)&qin[oidx];
        }
        return;
    }

    const float* Qb = g_Q + (size_t)((b * HH + h) * SS) * HD;
    const float* Kb = g_K + (size_t)((b * HH + h) * SS) * HD;
    const float* Vb = g_V + (size_t)((b * HH + h) * HD) * SS;  // [d][s]

    // Load Q tile (cvt tf32)
#pragma unroll
    for (int i = 0; i < 4; i++) {
        int cidx = tid + 256 * i;
        int row = cidx >> 4;
        int ch = (cidx & 15) * 4;
        float4 a = *(const float4*)&Qb[(size_t)(q0 + row) * HD + ch];
        Qs[row][ch + 0] = tf32f(a.x);
        Qs[row][ch + 1] = tf32f(a.y);
        Qs[row][ch + 2] = tf32f(a.z);
        Qs[row][ch + 3] = tf32f(a.w);
    }
    if (tid < 64) { m_sh[tid] = -INFINITY; l_sh[tid] = 0.0f; }

    float acc[4][4];
#pragma unroll
    for (int j = 0; j < 4; j++)
#pragma unroll
        for (int c = 0; c < 4; c++) acc[j][c] = 0.0f;

    const int kend = min(klen, q0 + 64);

    for (int k0 = 0; k0 < kend; k0 += 64) {
        __syncthreads();  // prior PV done before overwrite
        // Load K [kpos][d] and Vt [d][kpos] tiles (both row-contiguous in gmem)
#pragma unroll
        for (int i = 0; i < 4; i++) {
            int cidx = tid + 256 * i;
            int row = cidx >> 4;
            int ch = (cidx & 15) * 4;
            float4 kv = *(const float4*)&Kb[(size_t)(k0 + row) * HD + ch];
            Ks[row][ch + 0] = tf32f(kv.x);
            Ks[row][ch + 1] = tf32f(kv.y);
            Ks[row][ch + 2] = tf32f(kv.z);
            Ks[row][ch + 3] = tf32f(kv.w);
            float4 vv = *(const float4*)&Vb[(size_t)row * SS + k0 + ch];
            Vt[row][ch + 0] = tf32f(vv.x);
            Vt[row][ch + 1] = tf32f(vv.y);
            Vt[row][ch + 2] = tf32f(vv.z);
            Vt[row][ch + 3] = tf32f(vv.w);
        }
        __syncthreads();

        // S = Q K^T via tf32 mma: warp computes rows [wy*16,+16) x cols [wx*32,+32)
        float s[4][4];
#pragma unroll
        for (int j = 0; j < 4; j++)
#pragma unroll
            for (int c = 0; c < 4; c++) s[j][c] = 0.0f;
#pragma unroll
        for (int ks = 0; ks < 8; ks++) {
            int kc = ks * 8;
            int r = wy * 16;
            unsigned a0 = __float_as_uint(Qs[r + g][kc + t]);
            unsigned a1 = __float_as_uint(Qs[r + 8 + g][kc + t]);
            unsigned a2 = __float_as_uint(Qs[r + g][kc + t + 4]);
            unsigned a3 = __float_as_uint(Qs[r + 8 + g][kc + t + 4]);
#pragma unroll
            for (int j = 0; j < 4; j++) {
                int nr = wx * 32 + j * 8 + g;
                unsigned b0 = __float_as_uint(Ks[nr][kc + t]);
                unsigned b1 = __float_as_uint(Ks[nr][kc + t + 4]);
                mma8(s[j][0], s[j][1], s[j][2], s[j][3], a0, a1, a2, a3, b0, b1);
            }
        }
        // scale + mask -> Ps
#pragma unroll
        for (int j = 0; j < 4; j++) {
            int c = wx * 32 + j * 8 + 2 * t;
#pragma unroll
            for (int half = 0; half < 2; half++) {
                int r = wy * 16 + g + half * 8;
                int qq = q0 + r;
#pragma unroll
                for (int cc = 0; cc < 2; cc++) {
                    int kk = k0 + c + cc;
                    float val = s[j][half * 2 + cc] * 0.125f;
                    if (kk > qq || kk >= klen) val = -INFINITY;
                    Ps[r][c + cc] = val;
                }
            }
        }
        __syncthreads();

        // Online softmax (fp32, unchanged): 4 lanes per row
        {
            int row = tid >> 2;
            int seg = tid & 3;
            float mloc = -INFINITY;
#pragma unroll
            for (int tt = 0; tt < 16; tt++)
                mloc = fmaxf(mloc, Ps[row][seg * 16 + tt]);
            mloc = fmaxf(mloc, __shfl_xor_sync(0xffffffffu, mloc, 1));
            mloc = fmaxf(mloc, __shfl_xor_sync(0xffffffffu, mloc, 2));
            float mold = m_sh[row];
            float mnew = fmaxf(mold, mloc);
            if (mnew == -INFINITY) {
#pragma unroll
                for (int tt = 0; tt < 16; tt++) Ps[row][seg * 16 + tt] = 0.0f;
                if (seg == 0) alpha_sh[row] = 1.0f;
            } else {
                float sum = 0.0f;
#pragma unroll
                for (int tt = 0; tt < 16; tt++) {
                    float p = __expf(Ps[row][seg * 16 + tt] - mnew);
                    Ps[row][seg * 16 + tt] = p;
                    sum += p;
                }
                sum += __shfl_xor_sync(0xffffffffu, sum, 1);
                sum += __shfl_xor_sync(0xffffffffu, sum, 2);
                float alpha = (mold == -INFINITY) ? 0.0f : __expf(mold - mnew);
                if (seg == 0) {
                    m_sh[row] = mnew;
                    l_sh[row] = l_sh[row] * alpha + sum;
                    alpha_sh[row] = alpha;
                }
            }
        }
        __syncthreads();

        // O = O*alpha + P @ V  (A = Ps rows, B = Vt col-major)
        float al0 = alpha_sh[wy * 16 + g];
        float al1 = alpha_sh[wy * 16 + g + 8];
#pragma unroll
        for (int j = 0; j < 4; j++) {
            acc[j][0] *= al0; acc[j][1] *= al0;
            acc[j][2] *= al1; acc[j][3] *= al1;
        }
#pragma unroll
        for (int ks = 0; ks < 8; ks++) {
            int kc = ks * 8;
            int r = wy * 16;
            unsigned a0 = tf32u(Ps[r + g][kc + t]);
            unsigned a1 = tf32u(Ps[r + 8 + g][kc + t]);
            unsigned a2 = tf32u(Ps[r + g][kc + t + 4]);
            unsigned a3 = tf32u(Ps[r + 8 + g][kc + t + 4]);
#pragma unroll
            for (int j = 0; j < 4; j++) {
                int nr = wx * 32 + j * 8 + g;   // d index
                unsigned b0 = __float_as_uint(Vt[nr][kc + t]);
                unsigned b1 = __float_as_uint(Vt[nr][kc + t + 4]);
                mma8(acc[j][0], acc[j][1], acc[j][2], acc[j][3], a0, a1, a2, a3, b0, b1);
            }
        }
    }

    // Epilogue: normalize, residual, query-padding override.
#pragma unroll
    for (int j = 0; j < 4; j++) {
        int c = wx * 32 + j * 8 + 2 * t;  // d within head
#pragma unroll
        for (int half = 0; half < 2; half++) {
            int rloc = wy * 16 + g + half * 8;
            int qq = q0 + rloc;
            float l = l_sh[rloc];
            float inv = (l > 0.0f) ? (1.0f / l) : 0.0f;
            size_t oidx = (size_t)(b * SS + qq) * DD + h * HD + c;
            float2 r2 = *(const float2*)&qin[oidx];
            float2 o;
            if (qq >= qlen) {
                o = r2;
            } else {
                o.x = acc[j][half * 2 + 0] * inv + r2.x;
                o.y = acc[j][half * 2 + 1] * inv + r2.y;
            }
            *(float2*)&out[oidx] = o;
        }
    }
}

// ---------------------------------------------------------------------------
extern "C" void kernel_launch(void* const* d_in, const int* in_sizes, int n_in,
                              void* d_out, int out_size) {
    const float* q  = (const float*)d_in[0];
    const float* k  = (const float*)d_in[1];
    const float* v  = (const float*)d_in[2];
    const float* Wq = (const float*)d_in[3];
    const float* bq = (const float*)d_in[4];
    const float* Wk = (const float*)d_in[5];
    const float* bk = (const float*)d_in[6];
    const float* Wv = (const float*)d_in[7];
    const float* bv = (const float*)d_in[8];
    const unsigned char* km = (const unsigned char*)d_in[9];
    const unsigned char* qm = (const unsigned char*)d_in[10];
    float* out = (float*)d_out;

    static bool attr_set = false;
    if (!attr_set) {
        cudaFuncSetAttribute(attn_kernel,
                             cudaFuncAttributeMaxDynamicSharedMemorySize,
                             ATTN_SMEM_FLOATS * (int)sizeof(float));
        attr_set = true;
    }

    len_kernel<<<BB, 256>>>(km, qm);

    dim3 pg(DD / 64, (BB * SS) / 128);
    proj_kernel<<<pg, 256>>>(q, Wq, bq, 0);
    proj_kernel<<<pg, 256>>>(k, Wk, bk, 1);
    proj_kernel<<<pg, 256>>>(v, Wv, bv, 2);

    dim3 ag(SS / 64, HH, BB);
    attn_kernel<<<ag, 256, ATTN_SMEM_FLOATS * (int)sizeof(float)>>>(q, out);
}

// round 8
// speedup vs baseline: 3.6763x; 1.5128x over previous
#include <cuda_runtime.h>
#include <math.h>
#include <stdint.h>

#define BB 2
#define SS 2048
#define DD 1024
#define HH 16
#define HD 64

// Single dynamic-smem declaration shared by all kernels.
extern __shared__ char dynsmem[];

// Scratch: projected Q,K in [B,H,S,HD]; V transposed in [B,H,HD,S]
__device__ float g_Q[BB * HH * SS * HD];
__device__ float g_K[BB * HH * SS * HD];
__device__ float g_V[BB * HH * SS * HD];   // [B,H,HD,S] layout!
__device__ int g_klen[BB];
__device__ int g_qlen[BB];

// ---------------------------------------------------------------------------
// helpers
// ---------------------------------------------------------------------------
__device__ __forceinline__ uint32_t smem_u32(const void* p) {
    uint32_t a;
    asm("{ .reg .u64 t; cvta.to.shared.u64 t, %1; cvt.u32.u64 %0, t; }" : "=r"(a) : "l"(p));
    return a;
}
#define SWZ128(x) ((x) ^ (((x) >> 3) & 0x70))

__device__ __forceinline__ void cp16(uint32_t dst, const void* src) {
    asm volatile("cp.async.cg.shared.global [%0], [%1], 16;" :: "r"(dst), "l"(src) : "memory");
}
#define CP_COMMIT() asm volatile("cp.async.commit_group;" ::: "memory")
#define CP_WAIT0() asm volatile("cp.async.wait_group 0;" ::: "memory")
#define CP_WAIT1() asm volatile("cp.async.wait_group 1;" ::: "memory")

__device__ __forceinline__ unsigned tf32u(float x) {
    unsigned u; asm("cvt.rna.tf32.f32 %0, %1;" : "=r"(u) : "f"(x)); return u;
}
__device__ __forceinline__ float tf32f(float x) {
    return __uint_as_float(tf32u(x));
}
__device__ __forceinline__ void mma8(float& c0, float& c1, float& c2, float& c3,
                                     unsigned a0, unsigned a1, unsigned a2, unsigned a3,
                                     unsigned b0, unsigned b1) {
    asm volatile(
        "mma.sync.aligned.m16n8k8.row.col.f32.tf32.tf32.f32 "
        "{%0,%1,%2,%3},{%4,%5,%6,%7},{%8,%9},{%0,%1,%2,%3};"
        : "+f"(c0), "+f"(c1), "+f"(c2), "+f"(c3)
        : "r"(a0), "r"(a1), "r"(a2), "r"(a3), "r"(b0), "r"(b1));
}

// ---------------------------------------------------------------------------
// Mask lengths (dtype-robust: bool-1B or int32-4B; counts nonzero bytes).
// ---------------------------------------------------------------------------
__global__ void len_kernel(const unsigned char* __restrict__ km,
                           const unsigned char* __restrict__ qm) {
    int b = blockIdx.x;
    __shared__ int sk[256];
    __shared__ int sq[256];
    int tid = threadIdx.x;
    int wk = (km[1] | km[2] | km[3]) ? 1 : 4;
    int wq = (qm[1] | qm[2] | qm[3]) ? 1 : 4;
    int ck = 0, cq = 0;
    for (int i = tid; i < SS * wk; i += 256) ck += (km[(size_t)b * SS * wk + i] != 0);
    for (int i = tid; i < SS * wq; i += 256) cq += (qm[(size_t)b * SS * wq + i] != 0);
    sk[tid] = ck; sq[tid] = cq;
    __syncthreads();
    for (int s = 128; s > 0; s >>= 1) {
        if (tid < s) { sk[tid] += sk[tid + s]; sq[tid] += sq[tid + s]; }
        __syncthreads();
    }
    if (tid == 0) { g_klen[b] = sk[0]; g_qlen[b] = sq[0]; }
}

// ---------------------------------------------------------------------------
// Projection GEMM, tf32 mma.sync. BM=128, BN=128 (2 heads), BK=32.
// 8 warps in 4(m)x2(n); warp tile 32x64. 2-stage cp.async double buffer.
// Swizzled smem (SW128 pattern) -> conflict-free fragment LDS.
// blockIdx.z selects projection: 0->g_Q, 1->g_K, 2->g_V ([B,H,HD,S]).
// ---------------------------------------------------------------------------
#define PSTAGE 32768         // A 16KB + B 16KB
#define PB_OFF 16384
#define PROJ_SMEM (2 * PSTAGE)

__global__ __launch_bounds__(256, 2) void proj_kernel(
    const float* __restrict__ q, const float* __restrict__ k, const float* __restrict__ v,
    const float* __restrict__ Wq, const float* __restrict__ Wk, const float* __restrict__ Wv,
    const float* __restrict__ bq, const float* __restrict__ bk, const float* __restrict__ bv) {
    char* smem = dynsmem;
    const uint32_t sb = smem_u32(smem);
    const int tid = threadIdx.x;
    const int lane = tid & 31;
    const int wid = tid >> 5;
    const int g = lane >> 2;
    const int t = lane & 3;
    const int wy = wid & 3;    // m band (32 rows)
    const int wx = wid >> 2;   // n half (64 cols)

    const int which = blockIdx.z;
    const float* X = (which == 0) ? q : (which == 1) ? k : v;
    const float* W = (which == 0) ? Wq : (which == 1) ? Wk : Wv;
    const float* bias = (which == 0) ? bq : (which == 1) ? bk : bv;
    float* dst = (which == 0) ? g_Q : (which == 1) ? g_K : g_V;

    const int n0 = blockIdx.x * 128;
    const int m0 = blockIdx.y * 128;

    const int r0 = tid >> 3;         // 0..31, +32 per i
    const int cb = (tid & 7) * 16;   // byte col of 16B chunk in 128B row

    float acc[2][8][4] = {};

    auto load_tile = [&](int kt, int stage) {
        const int kf = kt * 32 + (cb >> 2);
        const uint32_t abase = sb + stage * PSTAGE;
#pragma unroll
        for (int i = 0; i < 4; i++) {
            int r = r0 + 32 * i;
            uint32_t sw = SWZ128((uint32_t)(r * 128 + cb));
            cp16(abase + sw, X + (size_t)(m0 + r) * DD + kf);
            cp16(abase + PB_OFF + sw, W + (size_t)(n0 + r) * DD + kf);
        }
    };

    load_tile(0, 0); CP_COMMIT();
    load_tile(1, 1); CP_COMMIT();

    for (int kt = 0; kt < 32; kt++) {
        const int st = kt & 1;
        if (kt < 30) CP_WAIT1(); else CP_WAIT0();
        __syncthreads();

        const char* A = smem + st * PSTAGE;
        const char* Bm = A + PB_OFF;
#pragma unroll
        for (int ks = 0; ks < 4; ks++) {
            const int kc = ks * 8;
            unsigned a[2][4];
#pragma unroll
            for (int mi = 0; mi < 2; mi++) {
                int r = wy * 32 + mi * 16;
                a[mi][0] = __float_as_uint(*(const float*)(A + SWZ128((uint32_t)((r + g) * 128 + (kc + t) * 4))));
                a[mi][1] = __float_as_uint(*(const float*)(A + SWZ128((uint32_t)((r + 8 + g) * 128 + (kc + t) * 4))));
                a[mi][2] = __float_as_uint(*(const float*)(A + SWZ128((uint32_t)((r + g) * 128 + (kc + t + 4) * 4))));
                a[mi][3] = __float_as_uint(*(const float*)(A + SWZ128((uint32_t)((r + 8 + g) * 128 + (kc + t + 4) * 4))));
            }
#pragma unroll
            for (int j = 0; j < 8; j++) {
                int nr = wx * 64 + j * 8 + g;
                unsigned b0 = __float_as_uint(*(const float*)(Bm + SWZ128((uint32_t)(nr * 128 + (kc + t) * 4))));
                unsigned b1 = __float_as_uint(*(const float*)(Bm + SWZ128((uint32_t)(nr * 128 + (kc + t + 4) * 4))));
                mma8(acc[0][j][0], acc[0][j][1], acc[0][j][2], acc[0][j][3],
                     a[0][0], a[0][1], a[0][2], a[0][3], b0, b1);
                mma8(acc[1][j][0], acc[1][j][1], acc[1][j][2], acc[1][j][3],
                     a[1][0], a[1][1], a[1][2], a[1][3], b0, b1);
            }
        }
        __syncthreads();
        if (kt + 2 < 32) { load_tile(kt + 2, st); CP_COMMIT(); }
    }

    // Epilogue: bias + store
#pragma unroll
    for (int j = 0; j < 8; j++) {
        const int cglob = n0 + wx * 64 + j * 8 + 2 * t;
        const int h = cglob >> 6;
        const int hd = cglob & 63;
        const float b0v = bias[cglob];
        const float b1v = bias[cglob + 1];
#pragma unroll
        for (int mi = 0; mi < 2; mi++) {
#pragma unroll
            for (int half = 0; half < 2; half++) {
                int r = m0 + wy * 32 + mi * 16 + g + half * 8;
                int b = r >> 11;
                int s = r & (SS - 1);
                float v0 = acc[mi][j][half * 2 + 0] + b0v;
                float v1 = acc[mi][j][half * 2 + 1] + b1v;
                if (which == 2) {
                    float* vb2 = dst + ((size_t)(b * HH + h) * HD) * SS;
                    vb2[(size_t)hd * SS + s] = v0;
                    vb2[(size_t)(hd + 1) * SS + s] = v1;
                } else {
                    *(float2*)&dst[((size_t)((b * HH + h) * SS) + s) * HD + hd] =
                        make_float2(v0, v1);
                }
            }
        }
    }
}

// ---------------------------------------------------------------------------
// Flash attention, tf32 mma.sync, cp.async double-buffered K/V tiles.
// K/V fed to MMA as raw fp32 bits (HW tf32 truncation); Q and P use rna cvt.
// ---------------------------------------------------------------------------
#define ALD 68
#define ATILE (64 * ALD)     // floats per tile
#define ATTN_SMEM_FLOATS (6 * ATILE + 3 * 64)

__global__ __launch_bounds__(256) void attn_kernel(
    const float* __restrict__ qin, float* __restrict__ out) {
    float* smf = (float*)dynsmem;
    const uint32_t sb = smem_u32(dynsmem);
    float (*Qs)[ALD] = (float(*)[ALD])(smf);
    float* m_sh = smf + 6 * ATILE;
    float* l_sh = m_sh + 64;
    float* alpha_sh = l_sh + 64;
    // tiles: Ks stage0 at +1*ATILE, stage1 at +2*ATILE; Vt at +3,+4; Ps at +5

    const int qt = blockIdx.x;
    const int h  = blockIdx.y;
    const int b  = blockIdx.z;
    const int q0 = qt * 64;
    const int klen = g_klen[b];
    const int qlen = g_qlen[b];

    const int tid = threadIdx.x;
    const int lane = tid & 31;
    const int wid = tid >> 5;
    const int g = lane >> 2;
    const int t = lane & 3;
    const int wy = wid & 3;
    const int wx = wid >> 2;

    if (q0 >= qlen) {
        int lrow = tid >> 2;
        int dseg = (tid & 3) * 16;
#pragma unroll
        for (int c = 0; c < 4; c++) {
            size_t oidx = (size_t)(b * SS + q0 + lrow) * DD + h * HD + dseg + 4 * c;
            *(float4*)&out[oidx] = *(const float4*)&qin[oidx];
        }
        return;
    }

    const float* Qb = g_Q + (size_t)((b * HH + h) * SS) * HD;
    const float* Kb = g_K + (size_t)((b * HH + h) * SS) * HD;
    const float* Vb = g_V + (size_t)((b * HH + h) * HD) * SS;

    const int kend = min(klen, q0 + 64);
    const int nt = (kend + 63) >> 6;

    auto load_kv = [&](int ti, int st) {
        const int k0 = ti * 64;
        const uint32_t kbase = sb + (uint32_t)(1 + st) * ATILE * 4;
        const uint32_t vbase = sb + (uint32_t)(3 + st) * ATILE * 4;
#pragma unroll
        for (int i = 0; i < 4; i++) {
            int id = tid + 256 * i;
            int row = id >> 4;
            int cf = (id & 15) * 4;
            cp16(kbase + (uint32_t)(row * ALD + cf) * 4, Kb + (size_t)(k0 + row) * HD + cf);
            cp16(vbase + (uint32_t)(row * ALD + cf) * 4, Vb + (size_t)row * SS + k0 + cf);
        }
    };

    load_kv(0, 0); CP_COMMIT();

    // Load Q tile (rna tf32 cvt)
#pragma unroll
    for (int i = 0; i < 4; i++) {
        int cidx = tid + 256 * i;
        int row = cidx >> 4;
        int ch = (cidx & 15) * 4;
        float4 a = *(const float4*)&Qb[(size_t)(q0 + row) * HD + ch];
        Qs[row][ch + 0] = tf32f(a.x);
        Qs[row][ch + 1] = tf32f(a.y);
        Qs[row][ch + 2] = tf32f(a.z);
        Qs[row][ch + 3] = tf32f(a.w);
    }
    if (tid < 64) { m_sh[tid] = -INFINITY; l_sh[tid] = 0.0f; }

    float acc[4][4] = {};
    float (*Ps)[ALD] = (float(*)[ALD])(smf + 5 * ATILE);

    for (int ti = 0; ti < nt; ti++) {
        const int k0 = ti * 64;
        const int st = ti & 1;
        __syncthreads();   // prior PV reads of this stage done; Q/stats visible on ti=0
        if (ti + 1 < nt) { load_kv(ti + 1, (ti + 1) & 1); CP_COMMIT(); CP_WAIT1(); }
        else CP_WAIT0();
        __syncthreads();

        float (*Ks)[ALD] = (float(*)[ALD])(smf + (1 + st) * ATILE);
        float (*Vt)[ALD] = (float(*)[ALD])(smf + (3 + st) * ATILE);

        // S = Q K^T
        float s[4][4] = {};
#pragma unroll
        for (int ks = 0; ks < 8; ks++) {
            int kc = ks * 8;
            int r = wy * 16;
            unsigned a0 = __float_as_uint(Qs[r + g][kc + t]);
            unsigned a1 = __float_as_uint(Qs[r + 8 + g][kc + t]);
            unsigned a2 = __float_as_uint(Qs[r + g][kc + t + 4]);
            unsigned a3 = __float_as_uint(Qs[r + 8 + g][kc + t + 4]);
#pragma unroll
            for (int j = 0; j < 4; j++) {
                int nr = wx * 32 + j * 8 + g;
                unsigned b0 = __float_as_uint(Ks[nr][kc + t]);
                unsigned b1 = __float_as_uint(Ks[nr][kc + t + 4]);
                mma8(s[j][0], s[j][1], s[j][2], s[j][3], a0, a1, a2, a3, b0, b1);
            }
        }
        // scale + mask -> Ps
#pragma unroll
        for (int j = 0; j < 4; j++) {
            int c = wx * 32 + j * 8 + 2 * t;
#pragma unroll
            for (int half = 0; half < 2; half++) {
                int r = wy * 16 + g + half * 8;
                int qq = q0 + r;
#pragma unroll
                for (int cc = 0; cc < 2; cc++) {
                    int kk = k0 + c + cc;
                    float val = s[j][half * 2 + cc] * 0.125f;
                    if (kk > qq || kk >= klen) val = -INFINITY;
                    Ps[r][c + cc] = val;
                }
            }
        }
        __syncthreads();

        // Online softmax (fp32)
        {
            int row = tid >> 2;
            int seg = tid & 3;
            float mloc = -INFINITY;
#pragma unroll
            for (int tt = 0; tt < 16; tt++)
                mloc = fmaxf(mloc, Ps[row][seg * 16 + tt]);
            mloc = fmaxf(mloc, __shfl_xor_sync(0xffffffffu, mloc, 1));
            mloc = fmaxf(mloc, __shfl_xor_sync(0xffffffffu, mloc, 2));
            float mold = m_sh[row];
            float mnew = fmaxf(mold, mloc);
            if (mnew == -INFINITY) {
#pragma unroll
                for (int tt = 0; tt < 16; tt++) Ps[row][seg * 16 + tt] = 0.0f;
                if (seg == 0) alpha_sh[row] = 1.0f;
            } else {
                float sum = 0.0f;
#pragma unroll
                for (int tt = 0; tt < 16; tt++) {
                    float p = __expf(Ps[row][seg * 16 + tt] - mnew);
                    Ps[row][seg * 16 + tt] = p;
                    sum += p;
                }
                sum += __shfl_xor_sync(0xffffffffu, sum, 1);
                sum += __shfl_xor_sync(0xffffffffu, sum, 2);
                float alpha = (mold == -INFINITY) ? 0.0f : __expf(mold - mnew);
                if (seg == 0) {
                    m_sh[row] = mnew;
                    l_sh[row] = l_sh[row] * alpha + sum;
                    alpha_sh[row] = alpha;
                }
            }
        }
        __syncthreads();

        // O = O*alpha + P @ V
        float al0 = alpha_sh[wy * 16 + g];
        float al1 = alpha_sh[wy * 16 + g + 8];
#pragma unroll
        for (int j = 0; j < 4; j++) {
            acc[j][0] *= al0; acc[j][1] *= al0;
            acc[j][2] *= al1; acc[j][3] *= al1;
        }
#pragma unroll
        for (int ks = 0; ks < 8; ks++) {
            int kc = ks * 8;
            int r = wy * 16;
            unsigned a0 = tf32u(Ps[r + g][kc + t]);
            unsigned a1 = tf32u(Ps[r + 8 + g][kc + t]);
            unsigned a2 = tf32u(Ps[r + g][kc + t + 4]);
            unsigned a3 = tf32u(Ps[r + 8 + g][kc + t + 4]);
#pragma unroll
            for (int j = 0; j < 4; j++) {
                int nr = wx * 32 + j * 8 + g;
                unsigned b0 = __float_as_uint(Vt[nr][kc + t]);
                unsigned b1 = __float_as_uint(Vt[nr][kc + t + 4]);
                mma8(acc[j][0], acc[j][1], acc[j][2], acc[j][3], a0, a1, a2, a3, b0, b1);
            }
        }
    }

    // Epilogue: normalize, residual, query-padding override.
#pragma unroll
    for (int j = 0; j < 4; j++) {
        int c = wx * 32 + j * 8 + 2 * t;
#pragma unroll
        for (int half = 0; half < 2; half++) {
            int rloc = wy * 16 + g + half * 8;
            int qq = q0 + rloc;
            float l = l_sh[rloc];
            float inv = (l > 0.0f) ? (1.0f / l) : 0.0f;
            size_t oidx = (size_t)(b * SS + qq) * DD + h * HD + c;
            float2 r2 = *(const float2*)&qin[oidx];
            float2 o;
            if (qq >= qlen) {
                o = r2;
            } else {
                o.x = acc[j][half * 2 + 0] * inv + r2.x;
                o.y = acc[j][half * 2 + 1] * inv + r2.y;
            }
            *(float2*)&out[oidx] = o;
        }
    }
}

// ---------------------------------------------------------------------------
extern "C" void kernel_launch(void* const* d_in, const int* in_sizes, int n_in,
                              void* d_out, int out_size) {
    const float* q  = (const float*)d_in[0];
    const float* k  = (const float*)d_in[1];
    const float* v  = (const float*)d_in[2];
    const float* Wq = (const float*)d_in[3];
    const float* bq = (const float*)d_in[4];
    const float* Wk = (const float*)d_in[5];
    const float* bk = (const float*)d_in[6];
    const float* Wv = (const float*)d_in[7];
    const float* bv = (const float*)d_in[8];
    const unsigned char* km = (const unsigned char*)d_in[9];
    const unsigned char* qm = (const unsigned char*)d_in[10];
    float* out = (float*)d_out;

    static bool attr_set = false;
    if (!attr_set) {
        cudaFuncSetAttribute(attn_kernel,
                             cudaFuncAttributeMaxDynamicSharedMemorySize,
                             ATTN_SMEM_FLOATS * (int)sizeof(float));
        cudaFuncSetAttribute(proj_kernel,
                             cudaFuncAttributeMaxDynamicSharedMemorySize,
                             PROJ_SMEM);
        attr_set = true;
    }

    len_kernel<<<BB, 256>>>(km, qm);

    dim3 pg(DD / 128, (BB * SS) / 128, 3);
    proj_kernel<<<pg, 256, PROJ_SMEM>>>(q, k, v, Wq, Wk, Wv, bq, bk, bv);

    dim3 ag(SS / 64, HH, BB);
    attn_kernel<<<ag, 256, ATTN_SMEM_FLOATS * (int)sizeof(float)>>>(q, out);
}